// round 8
// baseline (speedup 1.0000x reference)
#include <cuda_runtime.h>
#include <cuda_bf16.h>
#include <cstdint>

// Fixed shapes: B=2, H=8, N=256, D=64.  One CTA (512 thr, 16 warps) per query.
// Warp w = (wk = w>>1: k-slab of 32 rows, wd = w&1: j-half for GEMM1 / d-half for GEMM2).
#define NQ 256
#define DD 64
#define NPANEL 4

// 128B rows + XOR swizzle (bits[4:6] ^= bits[7:9]) -> conflict-free ldmatrix.
#define SWZ(x) ((x) ^ (((x) >> 3) & 0x70))

static constexpr uint32_t OFF_K2H = 0;        // [256 k][64 d] bf16 hi (32 KB)
static constexpr uint32_t OFF_K2L = 32768;
static constexpr uint32_t OFF_QHH = 65536;    // [64 j][64 d] bf16 hi, per panel (8 KB)
static constexpr uint32_t OFF_QHL = 73728;
static constexpr uint32_t OFF_V1H = 81920;    // [64 j][64 d] bf16 hi, per panel (8 KB)
static constexpr uint32_t OFF_V1L = 90112;
static constexpr uint32_t OFF_PH  = 98304;    // [256 k][64 j-local] bf16 hi (32 KB)
static constexpr uint32_t OFF_PL  = 131072;
static constexpr uint32_t OFF_SRED = 163840;  // [16 warps][32 d] fp32 (2 KB)
static constexpr uint32_t OFF_SLP  = 165888;  // [16] fp32
static constexpr uint32_t SMEM_BYTES = 165952;

// ---------------- PTX helpers ----------------------------------------------
__device__ __forceinline__ uint32_t smem_u32(const void* p) {
    uint32_t a;
    asm("{ .reg .u64 t; cvta.to.shared.u64 t, %1; cvt.u32.u64 %0, t; }" : "=r"(a) : "l"(p));
    return a;
}
__device__ __forceinline__ float ex2f(float x) {
    float y; asm("ex2.approx.ftz.f32 %0, %1;" : "=f"(y) : "f"(x)); return y;
}
__device__ __forceinline__ void ldsm_x4(uint32_t* r, uint32_t addr) {
    asm volatile("ldmatrix.sync.aligned.m8n8.x4.shared.b16 {%0,%1,%2,%3}, [%4];"
                 : "=r"(r[0]), "=r"(r[1]), "=r"(r[2]), "=r"(r[3]) : "r"(addr));
}
__device__ __forceinline__ void ldsm_x4_t(uint32_t* r, uint32_t addr) {
    asm volatile("ldmatrix.sync.aligned.m8n8.x4.trans.shared.b16 {%0,%1,%2,%3}, [%4];"
                 : "=r"(r[0]), "=r"(r[1]), "=r"(r[2]), "=r"(r[3]) : "r"(addr));
}
__device__ __forceinline__ void mma16816(float* c, const uint32_t* a, uint32_t b0, uint32_t b1) {
    asm volatile("mma.sync.aligned.m16n8k16.row.col.f32.bf16.bf16.f32 "
                 "{%0,%1,%2,%3}, {%4,%5,%6,%7}, {%8,%9}, {%0,%1,%2,%3};"
                 : "+f"(c[0]), "+f"(c[1]), "+f"(c[2]), "+f"(c[3])
                 : "r"(a[0]), "r"(a[1]), "r"(a[2]), "r"(a[3]), "r"(b0), "r"(b1));
}
__device__ __forceinline__ void split2(float x, float y, uint32_t& h, uint32_t& l) {
    __nv_bfloat162 h2 = __floats2bfloat162_rn(x, y);
    __nv_bfloat162 l2 = __floats2bfloat162_rn(x - __low2float(h2), y - __high2float(h2));
    h = *(uint32_t*)&h2; l = *(uint32_t*)&l2;
}

// ---------------- Kernel ----------------------------------------------------
__global__ __launch_bounds__(512, 1)
void trisimp_mma2_kernel(const float* __restrict__ q,  const float* __restrict__ k1,
                         const float* __restrict__ v1, const float* __restrict__ k2,
                         const float* __restrict__ v2, float* __restrict__ out)
{
    extern __shared__ char smem[];
    const uint32_t sb = smem_u32(smem);
    const int tid = threadIdx.x, w = tid >> 5, lid = tid & 31;
    const int wk = w >> 1, wd = w & 1;            // k-slab, j/d-half
    const int g = lid >> 2, t = lid & 3;

    const int bhq = blockIdx.x, qi = bhq & 255, bh = bhq >> 8;
    const size_t base = (size_t)bh * NQ * DD;
    const float* Qrow = q  + base + (size_t)qi * DD;
    const float* K1g  = k1 + base;
    const float* V1g  = v1 + base;
    const float* K2g  = k2 + base;
    const float* V2g  = v2 + base;

    // per-lane ldmatrix offsets (row, 16B-chunk) before swizzle
    const uint32_t lmA_r = (uint32_t)(lid & 15), lmA_c = (uint32_t)(lid >> 4) * 16;
    const uint32_t lmB_r = (uint32_t)((lid >> 4) * 8 + (lid & 7)), lmB_c = (uint32_t)((lid >> 3) & 1) * 16;

    // ---- stage K2 hi/lo once: [k][64 d] 128B swizzled rows ----
    {
        const float2* K2g2 = (const float2*)K2g;
        const int dp = tid & 31;                  // const per thread (512 % 32 == 0)
        for (int e2 = tid; e2 < NQ * 32; e2 += 512) {
            const int r = e2 >> 5;
            const float2 x = K2g2[e2];
            uint32_t h, l; split2(x.x, x.y, h, l);
            const uint32_t off = SWZ((uint32_t)r * 128 + (uint32_t)dp * 4);
            *(uint32_t*)(smem + OFF_K2H + off) = h;
            *(uint32_t*)(smem + OFF_K2L + off) = l;
        }
    }

    float o[2][4][4];                             // D2 accum: [mt][d8-tile][frag]
    #pragma unroll
    for (int mt = 0; mt < 2; ++mt)
        #pragma unroll
        for (int nt = 0; nt < 4; ++nt)
            #pragma unroll
            for (int r = 0; r < 4; ++r) o[mt][nt][r] = 0.f;
    float lsum = 0.f;

    #pragma unroll 1
    for (int p = 0; p < NPANEL; ++p) {
        __syncthreads();                          // prev panel fully consumed
        // ---- stage Qh and V1 panels: [64 j][64 d] hi/lo ----
        {
            const int dp = tid & 31;
            const float2 qp = ((const float2*)Qrow)[dp];
            const float qx = qp.x * 1.4426950408889634f;
            const float qy = qp.y * 1.4426950408889634f;
            const float2* K1p2 = (const float2*)(K1g + (size_t)p * 64 * DD);
            const float2* V1p2 = (const float2*)(V1g + (size_t)p * 64 * DD);
            for (int e2 = tid; e2 < 64 * 32; e2 += 512) {
                const int r = e2 >> 5;
                const uint32_t off = SWZ((uint32_t)r * 128 + (uint32_t)dp * 4);
                {
                    const float2 x = K1p2[e2];
                    uint32_t h, l; split2(qx * x.x, qy * x.y, h, l);
                    *(uint32_t*)(smem + OFF_QHH + off) = h;
                    *(uint32_t*)(smem + OFF_QHL + off) = l;
                }
                {
                    const float2 x = V1p2[e2];
                    uint32_t h, l; split2(x.x, x.y, h, l);
                    *(uint32_t*)(smem + OFF_V1H + off) = h;
                    *(uint32_t*)(smem + OFF_V1L + off) = l;
                }
            }
        }
        __syncthreads();                          // panels ready

        // ---- GEMM1: S[k32(wk), j32(wd half)] = sum_d K2*Qh (hi/lo 3-product) ----
        float s[2][4][4];
        #pragma unroll
        for (int mt = 0; mt < 2; ++mt)
            #pragma unroll
            for (int nt = 0; nt < 4; ++nt)
                #pragma unroll
                for (int r = 0; r < 4; ++r) s[mt][nt][r] = 0.f;

        #pragma unroll
        for (int kc = 0; kc < 4; ++kc) {          // d-chunks of 16
            uint32_t aH[2][4], aL[2][4];
            #pragma unroll
            for (int mt = 0; mt < 2; ++mt) {
                const uint32_t rb = (uint32_t)(32 * wk + 16 * mt + lmA_r) * 128
                                  + (uint32_t)kc * 32 + lmA_c;
                ldsm_x4(aH[mt], sb + OFF_K2H + SWZ(rb));
                ldsm_x4(aL[mt], sb + OFF_K2L + SWZ(rb));
            }
            #pragma unroll
            for (int cp = 0; cp < 2; ++cp) {      // j16 chunks of the j32 half
                uint32_t bH[4], bL[4];
                const uint32_t rb = (uint32_t)(32 * wd + 16 * cp + lmB_r) * 128
                                  + (uint32_t)kc * 32 + lmB_c;
                ldsm_x4(bH, sb + OFF_QHH + SWZ(rb));
                ldsm_x4(bL, sb + OFF_QHL + SWZ(rb));
                // interleave products across 4 accumulators
                #pragma unroll
                for (int h = 0; h < 2; ++h)
                    #pragma unroll
                    for (int mt = 0; mt < 2; ++mt)
                        mma16816(s[mt][2*cp+h], aH[mt], bH[2*h], bH[2*h+1]);
                #pragma unroll
                for (int h = 0; h < 2; ++h)
                    #pragma unroll
                    for (int mt = 0; mt < 2; ++mt)
                        mma16816(s[mt][2*cp+h], aH[mt], bL[2*h], bL[2*h+1]);
                #pragma unroll
                for (int h = 0; h < 2; ++h)
                    #pragma unroll
                    for (int mt = 0; mt < 2; ++mt)
                        mma16816(s[mt][2*cp+h], aL[mt], bH[2*h], bH[2*h+1]);
            }
        }

        // ---- exp2 + store P hi/lo to SMEM ([k][j-local 64], swizzled) ----
        #pragma unroll
        for (int mt = 0; mt < 2; ++mt) {
            #pragma unroll
            for (int nt = 0; nt < 4; ++nt) {
                float* cc = s[mt][nt];
                const float p0 = ex2f(cc[0]), p1 = ex2f(cc[1]);
                const float p2 = ex2f(cc[2]), p3 = ex2f(cc[3]);
                lsum += (p0 + p1) + (p2 + p3);
                uint32_t h0, l0, h1, l1;
                split2(p0, p1, h0, l0);           // row g
                split2(p2, p3, h1, l1);           // row g+8
                const uint32_t jb = (uint32_t)(32 * wd + 8 * nt + 2 * t) * 2;
                const uint32_t r0 = (uint32_t)(32 * wk + 16 * mt + g) * 128 + jb;
                const uint32_t r1 = r0 + 8 * 128;
                *(uint32_t*)(smem + OFF_PH + SWZ(r0)) = h0;
                *(uint32_t*)(smem + OFF_PL + SWZ(r0)) = l0;
                *(uint32_t*)(smem + OFF_PH + SWZ(r1)) = h1;
                *(uint32_t*)(smem + OFF_PL + SWZ(r1)) = l1;
            }
        }
        __syncthreads();                          // full P panel visible

        // ---- GEMM2: D2[k32(wk), d32(wd half)] += sum_j P * V1 ----
        #pragma unroll
        for (int jc = 0; jc < 4; ++jc) {          // j16 chunks of the 64-j panel
            uint32_t paH[2][4], paL[2][4];
            #pragma unroll
            for (int mt = 0; mt < 2; ++mt) {
                const uint32_t rb = (uint32_t)(32 * wk + 16 * mt + lmA_r) * 128
                                  + (uint32_t)jc * 32 + lmA_c;
                ldsm_x4(paH[mt], sb + OFF_PH + SWZ(rb));
                ldsm_x4(paL[mt], sb + OFF_PL + SWZ(rb));
            }
            #pragma unroll
            for (int ntp = 0; ntp < 2; ++ntp) {   // d16 chunks of the d32 half
                uint32_t vH[4], vL[4];
                const uint32_t rb = (uint32_t)(16 * jc + lmA_r) * 128
                                  + (uint32_t)(64 * wd + 32 * ntp) + lmA_c;
                ldsm_x4_t(vH, sb + OFF_V1H + SWZ(rb));
                ldsm_x4_t(vL, sb + OFF_V1L + SWZ(rb));
                #pragma unroll
                for (int h = 0; h < 2; ++h)
                    #pragma unroll
                    for (int mt = 0; mt < 2; ++mt)
                        mma16816(o[mt][2*ntp+h], paH[mt], vH[2*h], vH[2*h+1]);
                #pragma unroll
                for (int h = 0; h < 2; ++h)
                    #pragma unroll
                    for (int mt = 0; mt < 2; ++mt)
                        mma16816(o[mt][2*ntp+h], paH[mt], vL[2*h], vL[2*h+1]);
                #pragma unroll
                for (int h = 0; h < 2; ++h)
                    #pragma unroll
                    for (int mt = 0; mt < 2; ++mt)
                        mma16816(o[mt][2*ntp+h], paL[mt], vH[2*h], vH[2*h+1]);
            }
        }
    }

    // ---- epilogue: out[d] = sum_k D2[k,d] * v2[k,d] / sum(exp) ----
    float* sRed = (float*)(smem + OFF_SRED);      // [16][32]
    float* sLp  = (float*)(smem + OFF_SLP);
    {
        const int k0 = 32 * wk + g;
        #pragma unroll
        for (int nt = 0; nt < 4; ++nt) {
            const int d0 = 32 * wd + 8 * nt + 2 * t;
            const float2 vA = *(const float2*)(V2g + (size_t)(k0)      * DD + d0);
            const float2 vB = *(const float2*)(V2g + (size_t)(k0 + 8)  * DD + d0);
            const float2 vC = *(const float2*)(V2g + (size_t)(k0 + 16) * DD + d0);
            const float2 vD = *(const float2*)(V2g + (size_t)(k0 + 24) * DD + d0);
            float r0 = o[0][nt][0]*vA.x + o[0][nt][2]*vB.x + o[1][nt][0]*vC.x + o[1][nt][2]*vD.x;
            float r1 = o[0][nt][1]*vA.y + o[0][nt][3]*vB.y + o[1][nt][1]*vC.y + o[1][nt][3]*vD.y;
            #pragma unroll
            for (int m = 4; m <= 16; m <<= 1) {   // reduce over g rows
                r0 += __shfl_xor_sync(0xffffffffu, r0, m);
                r1 += __shfl_xor_sync(0xffffffffu, r1, m);
            }
            if (g == 0) *(float2*)(sRed + w * 32 + 8 * nt + 2 * t) = make_float2(r0, r1);
        }
        #pragma unroll
        for (int m = 16; m; m >>= 1)
            lsum += __shfl_xor_sync(0xffffffffu, lsum, m);
        if (lid == 0) sLp[w] = lsum;
    }
    __syncthreads();

    if (tid < 64) {
        const int dh = tid >> 5, dl = tid & 31;
        float ssum = 0.f;
        #pragma unroll
        for (int kk = 0; kk < 8; ++kk) ssum += sRed[(2 * kk + dh) * 32 + dl];
        float l = 0.f;
        #pragma unroll
        for (int ww = 0; ww < 16; ++ww) l += sLp[ww];
        out[base + (size_t)qi * DD + tid] = ssum / l;
    }
}

extern "C" void kernel_launch(void* const* d_in, const int* in_sizes, int n_in,
                              void* d_out, int out_size)
{
    const float* q  = (const float*)d_in[0];
    const float* k1 = (const float*)d_in[1];
    const float* v1 = (const float*)d_in[2];
    const float* k2 = (const float*)d_in[3];
    const float* v2 = (const float*)d_in[4];
    float* out = (float*)d_out;

    (void)cudaFuncSetAttribute(trisimp_mma2_kernel,
                               cudaFuncAttributeMaxDynamicSharedMemorySize, SMEM_BYTES);
    trisimp_mma2_kernel<<<2 * 8 * NQ, 512, SMEM_BYTES>>>(q, k1, v1, k2, v2, out);
}

// round 10
// speedup vs baseline: 1.2903x; 1.2903x over previous
#include <cuda_runtime.h>
#include <cuda_bf16.h>
#include <cuda_fp16.h>
#include <cstdint>

// Fixed shapes: B=2, H=8, N=256, D=64.  One CTA (256 thr, 8 warps) per query.
// Warp w owns k-rows [32w, 32w+32).  GEMM1: bf16 hi/lo 3-product (log2-domain).
// GEMM2: fp16 2-product with per-warp ONLINE max (flash-style rescaling).
#define NQ 256
#define DD 64
#define NPANEL 4

#define SWZ(x) ((x) ^ (((x) >> 3) & 0x70))

static constexpr uint32_t OFF_K2H  = 0;        // [256 k][64 d] bf16 hi (32 KB)
static constexpr uint32_t OFF_K2L  = 32768;
static constexpr uint32_t OFF_QHH  = 65536;    // [64 j][64 d] bf16 hi, current panel (8 KB)
static constexpr uint32_t OFF_QHL  = 73728;
static constexpr uint32_t OFF_V1H  = 81920;    // [64 j][64 d] fp16 hi, current panel (8 KB)
static constexpr uint32_t OFF_V1L  = 90112;
static constexpr uint32_t OFF_RAWK = 98304;    // 2 x 16 KB raw fp32 K1 panels
static constexpr uint32_t OFF_RAWV = 131072;   // 2 x 16 KB raw fp32 V1 panels
static constexpr uint32_t OFF_SRED = 163840;   // [8 warps][64 d] fp32 (2 KB)
static constexpr uint32_t OFF_SLP  = 165888;   // [8] fp32 lsum
static constexpr uint32_t OFF_SM   = 165920;   // [8] fp32 per-warp max
static constexpr uint32_t SMEM_BYTES = 165952;

// ---------------- PTX helpers ----------------------------------------------
__device__ __forceinline__ uint32_t smem_u32(const void* p) {
    uint32_t a;
    asm("{ .reg .u64 t; cvta.to.shared.u64 t, %1; cvt.u32.u64 %0, t; }" : "=r"(a) : "l"(p));
    return a;
}
__device__ __forceinline__ float ex2f(float x) {
    float y; asm("ex2.approx.ftz.f32 %0, %1;" : "=f"(y) : "f"(x)); return y;
}
__device__ __forceinline__ void cp16(uint32_t dst, const void* src) {
    asm volatile("cp.async.cg.shared.global [%0], [%1], 16;" :: "r"(dst), "l"(src));
}
__device__ __forceinline__ void cp_commit() { asm volatile("cp.async.commit_group;"); }
__device__ __forceinline__ void cp_wait0()  { asm volatile("cp.async.wait_group 0;" ::: "memory"); }
__device__ __forceinline__ void ldsm_x4(uint32_t* r, uint32_t addr) {
    asm volatile("ldmatrix.sync.aligned.m8n8.x4.shared.b16 {%0,%1,%2,%3}, [%4];"
                 : "=r"(r[0]), "=r"(r[1]), "=r"(r[2]), "=r"(r[3]) : "r"(addr));
}
__device__ __forceinline__ void ldsm_x4_t(uint32_t* r, uint32_t addr) {
    asm volatile("ldmatrix.sync.aligned.m8n8.x4.trans.shared.b16 {%0,%1,%2,%3}, [%4];"
                 : "=r"(r[0]), "=r"(r[1]), "=r"(r[2]), "=r"(r[3]) : "r"(addr));
}
__device__ __forceinline__ void mma_bf(float* c, const uint32_t* a, uint32_t b0, uint32_t b1) {
    asm volatile("mma.sync.aligned.m16n8k16.row.col.f32.bf16.bf16.f32 "
                 "{%0,%1,%2,%3}, {%4,%5,%6,%7}, {%8,%9}, {%0,%1,%2,%3};"
                 : "+f"(c[0]), "+f"(c[1]), "+f"(c[2]), "+f"(c[3])
                 : "r"(a[0]), "r"(a[1]), "r"(a[2]), "r"(a[3]), "r"(b0), "r"(b1));
}
__device__ __forceinline__ void mma_hf(float* c, const uint32_t* a, uint32_t b0, uint32_t b1) {
    asm volatile("mma.sync.aligned.m16n8k16.row.col.f32.f16.f16.f32 "
                 "{%0,%1,%2,%3}, {%4,%5,%6,%7}, {%8,%9}, {%0,%1,%2,%3};"
                 : "+f"(c[0]), "+f"(c[1]), "+f"(c[2]), "+f"(c[3])
                 : "r"(a[0]), "r"(a[1]), "r"(a[2]), "r"(a[3]), "r"(b0), "r"(b1));
}
__device__ __forceinline__ void split2(float x, float y, uint32_t& h, uint32_t& l) {
    __nv_bfloat162 h2 = __floats2bfloat162_rn(x, y);
    __nv_bfloat162 l2 = __floats2bfloat162_rn(x - __low2float(h2), y - __high2float(h2));
    h = *(uint32_t*)&h2; l = *(uint32_t*)&l2;
}
__device__ __forceinline__ void split2h(float x, float y, uint32_t& h, uint32_t& l) {
    __half2 h2 = __floats2half2_rn(x, y);
    __half2 l2 = __floats2half2_rn(x - __half2float(__low2half(h2)),
                                   y - __half2float(__high2half(h2)));
    h = *(uint32_t*)&h2; l = *(uint32_t*)&l2;
}
__device__ __forceinline__ uint32_t packh2_sat(float x, float y) {   // x -> low half
    uint32_t r;
    asm("cvt.rn.satfinite.f16x2.f32 %0, %1, %2;" : "=r"(r) : "f"(y), "f"(x));
    return r;
}

// ---------------- Kernel ----------------------------------------------------
__global__ __launch_bounds__(256, 1)
void trisimp_mma4_kernel(const float* __restrict__ q,  const float* __restrict__ k1,
                         const float* __restrict__ v1, const float* __restrict__ k2,
                         const float* __restrict__ v2, float* __restrict__ out)
{
    extern __shared__ char smem[];
    const uint32_t sb = smem_u32(smem);
    const int tid = threadIdx.x, w = tid >> 5, lid = tid & 31;
    const int g = lid >> 2, t = lid & 3;

    const int bhq = blockIdx.x, qi = bhq & 255, bh = bhq >> 8;
    const size_t base = (size_t)bh * NQ * DD;
    const float* Qrow = q  + base + (size_t)qi * DD;
    const float* K1g  = k1 + base;
    const float* V1g  = v1 + base;
    const float* K2g  = k2 + base;
    const float* V2g  = v2 + base;

    // ---- prefetch panel 0 raw K1/V1 (16 KB each) via cp.async ----
    {
        const char* gK = (const char*)K1g;
        const char* gV = (const char*)V1g;
        for (int i = tid; i < 1024; i += 256) {
            cp16(sb + OFF_RAWK + (uint32_t)i * 16, gK + (size_t)i * 16);
            cp16(sb + OFF_RAWV + (uint32_t)i * 16, gV + (size_t)i * 16);
        }
        cp_commit();
    }

    const int dp = tid & 31;
    // ---- stage K2 hi/lo (overlaps cp.async flight) ----
    {
        const float2* K2g2 = (const float2*)K2g;
        for (int e2 = tid; e2 < NQ * 32; e2 += 256) {
            const int r = e2 >> 5;
            const float2 x = K2g2[e2];
            uint32_t h, l; split2(x.x, x.y, h, l);
            const uint32_t off = SWZ((uint32_t)r * 128 + (uint32_t)dp * 4);
            *(uint32_t*)(smem + OFF_K2H + off) = h;
            *(uint32_t*)(smem + OFF_K2L + off) = l;
        }
    }

    const float2 qme = ((const float2*)Qrow)[dp];
    const float qx = qme.x * 1.4426950408889634f;
    const float qy = qme.y * 1.4426950408889634f;

    const uint32_t lmA_r = (uint32_t)(lid & 15), lmA_c = (uint32_t)(lid >> 4) * 16;
    const uint32_t lmB_r = (uint32_t)((lid >> 4) * 8 + (lid & 7)), lmB_c = (uint32_t)((lid >> 3) & 1) * 16;

    float o[2][8][4];
    #pragma unroll
    for (int mt = 0; mt < 2; ++mt)
        #pragma unroll
        for (int nt = 0; nt < 8; ++nt)
            #pragma unroll
            for (int r = 0; r < 4; ++r) o[mt][nt][r] = 0.f;
    float lsum = 0.f;
    float mrun = -1e30f;                 // running per-warp max (log2 units)

    #pragma unroll 1
    for (int p = 0; p < NPANEL; ++p) {
        cp_wait0();
        __syncthreads();

        // ---- convert raw panel p: Qh (bf16 hi/lo) and V1 (fp16 hi/lo) ----
        {
            const float2* rk = (const float2*)(smem + OFF_RAWK + (uint32_t)(p & 1) * 16384);
            const float2* rv = (const float2*)(smem + OFF_RAWV + (uint32_t)(p & 1) * 16384);
            for (int e2 = tid; e2 < 64 * 32; e2 += 256) {
                const int r = e2 >> 5;
                const uint32_t off = SWZ((uint32_t)r * 128 + (uint32_t)dp * 4);
                {
                    const float2 x = rk[e2];
                    uint32_t h, l; split2(qx * x.x, qy * x.y, h, l);
                    *(uint32_t*)(smem + OFF_QHH + off) = h;
                    *(uint32_t*)(smem + OFF_QHL + off) = l;
                }
                {
                    const float2 x = rv[e2];
                    uint32_t h, l; split2h(x.x, x.y, h, l);
                    *(uint32_t*)(smem + OFF_V1H + off) = h;
                    *(uint32_t*)(smem + OFF_V1L + off) = l;
                }
            }
        }
        if (p < NPANEL - 1) {            // prefetch panel p+1 raw
            const char* gK = (const char*)(K1g + (size_t)(p + 1) * 64 * DD);
            const char* gV = (const char*)(V1g + (size_t)(p + 1) * 64 * DD);
            const uint32_t rb = (uint32_t)((p + 1) & 1) * 16384;
            for (int i = tid; i < 1024; i += 256) {
                cp16(sb + OFF_RAWK + rb + (uint32_t)i * 16, gK + (size_t)i * 16);
                cp16(sb + OFF_RAWV + rb + (uint32_t)i * 16, gV + (size_t)i * 16);
            }
            cp_commit();
        }
        __syncthreads();

        // ---- GEMM1: S[k32(w), j64] in log2 units (bf16 hi/lo, 3 products) ----
        float s[2][8][4];
        #pragma unroll
        for (int mt = 0; mt < 2; ++mt)
            #pragma unroll
            for (int nt = 0; nt < 8; ++nt)
                #pragma unroll
                for (int r = 0; r < 4; ++r) s[mt][nt][r] = 0.f;

        #pragma unroll
        for (int kc = 0; kc < 4; ++kc) {
            uint32_t aH[2][4], aL[2][4];
            #pragma unroll
            for (int mt = 0; mt < 2; ++mt) {
                const uint32_t rb = (uint32_t)(32 * w + 16 * mt + lmA_r) * 128
                                  + (uint32_t)kc * 32 + lmA_c;
                ldsm_x4(aH[mt], sb + OFF_K2H + SWZ(rb));
                ldsm_x4(aL[mt], sb + OFF_K2L + SWZ(rb));
            }
            #pragma unroll
            for (int cp = 0; cp < 4; ++cp) {
                uint32_t bH[4], bL[4];
                const uint32_t rb = (uint32_t)(16 * cp + lmB_r) * 128
                                  + (uint32_t)kc * 32 + lmB_c;
                ldsm_x4(bH, sb + OFF_QHH + SWZ(rb));
                ldsm_x4(bL, sb + OFF_QHL + SWZ(rb));
                #pragma unroll
                for (int h = 0; h < 2; ++h)
                    #pragma unroll
                    for (int mt = 0; mt < 2; ++mt)
                        mma_bf(s[mt][2*cp+h], aH[mt], bH[2*h], bH[2*h+1]);
                #pragma unroll
                for (int h = 0; h < 2; ++h)
                    #pragma unroll
                    for (int mt = 0; mt < 2; ++mt)
                        mma_bf(s[mt][2*cp+h], aH[mt], bL[2*h], bL[2*h+1]);
                #pragma unroll
                for (int h = 0; h < 2; ++h)
                    #pragma unroll
                    for (int mt = 0; mt < 2; ++mt)
                        mma_bf(s[mt][2*cp+h], aL[mt], bH[2*h], bH[2*h+1]);
            }
        }

        // ---- online max update: warp-wide max of this panel's logits ----
        {
            float pm = s[0][0][0];
            #pragma unroll
            for (int mt = 0; mt < 2; ++mt)
                #pragma unroll
                for (int nt = 0; nt < 8; ++nt)
                    #pragma unroll
                    for (int r = 0; r < 4; ++r) pm = fmaxf(pm, s[mt][nt][r]);
            #pragma unroll
            for (int m = 16; m; m >>= 1)
                pm = fmaxf(pm, __shfl_xor_sync(0xffffffffu, pm, m));
            const float mnew = fmaxf(mrun, pm);
            const float rsc = ex2f(mrun - mnew);     // 0 on first panel
            lsum *= rsc;
            #pragma unroll
            for (int mt = 0; mt < 2; ++mt)
                #pragma unroll
                for (int nt = 0; nt < 8; ++nt)
                    #pragma unroll
                    for (int r = 0; r < 4; ++r) o[mt][nt][r] *= rsc;
            mrun = mnew;
        }

        // ---- per j16-chunk: exp2(s - m) -> fp16 P (<=1), GEMM2 fp16 2-product ----
        #pragma unroll
        for (int c = 0; c < 4; ++c) {
            uint32_t paH[2][4];
            #pragma unroll
            for (int mt = 0; mt < 2; ++mt) {
                #pragma unroll
                for (int h = 0; h < 2; ++h) {
                    float* cc = s[mt][2 * c + h];
                    const float p0 = ex2f(cc[0] - mrun);
                    const float p1 = ex2f(cc[1] - mrun);
                    const float p2 = ex2f(cc[2] - mrun);
                    const float p3 = ex2f(cc[3] - mrun);
                    lsum += (p0 + p1) + (p2 + p3);
                    paH[mt][2*h]   = packh2_sat(p0, p1);   // rows g
                    paH[mt][2*h+1] = packh2_sat(p2, p3);   // rows g+8
                }
            }
            #pragma unroll
            for (int ntp = 0; ntp < 4; ++ntp) {
                uint32_t vH[4], vL[4];
                const uint32_t rb = (uint32_t)(16 * c + lmA_r) * 128
                                  + (uint32_t)ntp * 32 + lmA_c;
                ldsm_x4_t(vH, sb + OFF_V1H + SWZ(rb));
                ldsm_x4_t(vL, sb + OFF_V1L + SWZ(rb));
                #pragma unroll
                for (int h = 0; h < 2; ++h)
                    #pragma unroll
                    for (int mt = 0; mt < 2; ++mt)
                        mma_hf(o[mt][2*ntp+h], paH[mt], vH[2*h], vH[2*h+1]);
                #pragma unroll
                for (int h = 0; h < 2; ++h)
                    #pragma unroll
                    for (int mt = 0; mt < 2; ++mt)
                        mma_hf(o[mt][2*ntp+h], paH[mt], vL[2*h], vL[2*h+1]);
            }
        }
    }

    // ---- epilogue: combine warps with per-warp max rescale ----
    float* sRed = (float*)(smem + OFF_SRED);
    float* sLp  = (float*)(smem + OFF_SLP);
    float* sM   = (float*)(smem + OFF_SM);
    {
        const int k0 = 32 * w + g;
        #pragma unroll
        for (int nt = 0; nt < 8; ++nt) {
            const int d0 = 8 * nt + 2 * t;
            const float2 vA = *(const float2*)(V2g + (size_t)(k0)      * DD + d0);
            const float2 vB = *(const float2*)(V2g + (size_t)(k0 + 8)  * DD + d0);
            const float2 vC = *(const float2*)(V2g + (size_t)(k0 + 16) * DD + d0);
            const float2 vD = *(const float2*)(V2g + (size_t)(k0 + 24) * DD + d0);
            float r0 = o[0][nt][0]*vA.x + o[0][nt][2]*vB.x + o[1][nt][0]*vC.x + o[1][nt][2]*vD.x;
            float r1 = o[0][nt][1]*vA.y + o[0][nt][3]*vB.y + o[1][nt][1]*vC.y + o[1][nt][3]*vD.y;
            #pragma unroll
            for (int m = 4; m <= 16; m <<= 1) {
                r0 += __shfl_xor_sync(0xffffffffu, r0, m);
                r1 += __shfl_xor_sync(0xffffffffu, r1, m);
            }
            if (g == 0) *(float2*)(sRed + w * 64 + d0) = make_float2(r0, r1);
        }
        #pragma unroll
        for (int m = 16; m; m >>= 1)
            lsum += __shfl_xor_sync(0xffffffffu, lsum, m);
        if (lid == 0) { sLp[w] = lsum; sM[w] = mrun; }
    }
    __syncthreads();

    if (tid < 64) {
        float M = sM[0];
        #pragma unroll
        for (int ww = 1; ww < 8; ++ww) M = fmaxf(M, sM[ww]);
        float ssum = 0.f, l = 0.f;
        #pragma unroll
        for (int ww = 0; ww < 8; ++ww) {
            const float sc = ex2f(sM[ww] - M);
            ssum += sc * sRed[ww * 64 + tid];
            l    += sc * sLp[ww];
        }
        out[base + (size_t)qi * DD + tid] = ssum / l;
    }
}

extern "C" void kernel_launch(void* const* d_in, const int* in_sizes, int n_in,
                              void* d_out, int out_size)
{
    const float* q  = (const float*)d_in[0];
    const float* k1 = (const float*)d_in[1];
    const float* v1 = (const float*)d_in[2];
    const float* k2 = (const float*)d_in[3];
    const float* v2 = (const float*)d_in[4];
    float* out = (float*)d_out;

    (void)cudaFuncSetAttribute(trisimp_mma4_kernel,
                               cudaFuncAttributeMaxDynamicSharedMemorySize, SMEM_BYTES);
    trisimp_mma4_kernel<<<2 * 8 * NQ, 256, SMEM_BYTES>>>(q, k1, v1, k2, v2, out);
}

// round 11
// speedup vs baseline: 1.4809x; 1.1477x over previous
#include <cuda_runtime.h>
#include <cuda_bf16.h>
#include <cuda_fp16.h>
#include <cstdint>

// Fixed shapes: B=2, H=8, N=256, D=64.  One CTA (256 thr, 8 warps) per query.
// Warp w owns k-rows [32w, 32w+32).  GEMM1: bf16 hi/lo 3-product (log2-domain).
// GEMM2: fp16 1-product (P fp16 x V1 fp16) with per-warp online max.
#define NQ 256
#define DD 64
#define NPANEL 4

#define SWZ(x) ((x) ^ (((x) >> 3) & 0x70))

static constexpr uint32_t OFF_K2H  = 0;        // [256 k][64 d] bf16 hi (32 KB)
static constexpr uint32_t OFF_K2L  = 32768;
static constexpr uint32_t OFF_QHH  = 65536;    // [64 j][64 d] bf16 hi, current panel (8 KB)
static constexpr uint32_t OFF_QHL  = 73728;
static constexpr uint32_t OFF_V1H  = 81920;    // [64 j][64 d] fp16, current panel (8 KB)
static constexpr uint32_t OFF_RAWK = 90112;    // 2 x 16 KB raw fp32 K1 panels
static constexpr uint32_t OFF_RAWV = 122880;   // 2 x 16 KB raw fp32 V1 panels
static constexpr uint32_t OFF_SRED = 155648;   // [8 warps][64 d] fp32 (2 KB)
static constexpr uint32_t OFF_SLP  = 157696;   // [8] fp32 lsum
static constexpr uint32_t OFF_SM   = 157728;   // [8] fp32 per-warp max
static constexpr uint32_t SMEM_BYTES = 157760;

// ---------------- PTX helpers ----------------------------------------------
__device__ __forceinline__ uint32_t smem_u32(const void* p) {
    uint32_t a;
    asm("{ .reg .u64 t; cvta.to.shared.u64 t, %1; cvt.u32.u64 %0, t; }" : "=r"(a) : "l"(p));
    return a;
}
__device__ __forceinline__ float ex2f(float x) {
    float y; asm("ex2.approx.ftz.f32 %0, %1;" : "=f"(y) : "f"(x)); return y;
}
__device__ __forceinline__ void cp16(uint32_t dst, const void* src) {
    asm volatile("cp.async.cg.shared.global [%0], [%1], 16;" :: "r"(dst), "l"(src));
}
__device__ __forceinline__ void cp_commit() { asm volatile("cp.async.commit_group;"); }
__device__ __forceinline__ void cp_wait0()  { asm volatile("cp.async.wait_group 0;" ::: "memory"); }
__device__ __forceinline__ void ldsm_x4(uint32_t* r, uint32_t addr) {
    asm volatile("ldmatrix.sync.aligned.m8n8.x4.shared.b16 {%0,%1,%2,%3}, [%4];"
                 : "=r"(r[0]), "=r"(r[1]), "=r"(r[2]), "=r"(r[3]) : "r"(addr));
}
__device__ __forceinline__ void ldsm_x4_t(uint32_t* r, uint32_t addr) {
    asm volatile("ldmatrix.sync.aligned.m8n8.x4.trans.shared.b16 {%0,%1,%2,%3}, [%4];"
                 : "=r"(r[0]), "=r"(r[1]), "=r"(r[2]), "=r"(r[3]) : "r"(addr));
}
// NOTE: NOT volatile -- pure register ops; lets ptxas software-pipeline LDSM/MMA.
__device__ __forceinline__ void mma_bf(float* c, const uint32_t* a, uint32_t b0, uint32_t b1) {
    asm("mma.sync.aligned.m16n8k16.row.col.f32.bf16.bf16.f32 "
        "{%0,%1,%2,%3}, {%4,%5,%6,%7}, {%8,%9}, {%0,%1,%2,%3};"
        : "+f"(c[0]), "+f"(c[1]), "+f"(c[2]), "+f"(c[3])
        : "r"(a[0]), "r"(a[1]), "r"(a[2]), "r"(a[3]), "r"(b0), "r"(b1));
}
__device__ __forceinline__ void mma_hf(float* c, const uint32_t* a, uint32_t b0, uint32_t b1) {
    asm("mma.sync.aligned.m16n8k16.row.col.f32.f16.f16.f32 "
        "{%0,%1,%2,%3}, {%4,%5,%6,%7}, {%8,%9}, {%0,%1,%2,%3};"
        : "+f"(c[0]), "+f"(c[1]), "+f"(c[2]), "+f"(c[3])
        : "r"(a[0]), "r"(a[1]), "r"(a[2]), "r"(a[3]), "r"(b0), "r"(b1));
}
__device__ __forceinline__ void split2(float x, float y, uint32_t& h, uint32_t& l) {
    __nv_bfloat162 h2 = __floats2bfloat162_rn(x, y);
    __nv_bfloat162 l2 = __floats2bfloat162_rn(x - __low2float(h2), y - __high2float(h2));
    h = *(uint32_t*)&h2; l = *(uint32_t*)&l2;
}
__device__ __forceinline__ uint32_t packh2_sat(float x, float y) {   // x -> low half
    uint32_t r;
    asm("cvt.rn.satfinite.f16x2.f32 %0, %1, %2;" : "=r"(r) : "f"(y), "f"(x));
    return r;
}

// ---------------- Kernel ----------------------------------------------------
__global__ __launch_bounds__(256, 1)
void trisimp_mma5_kernel(const float* __restrict__ q,  const float* __restrict__ k1,
                         const float* __restrict__ v1, const float* __restrict__ k2,
                         const float* __restrict__ v2, float* __restrict__ out)
{
    extern __shared__ char smem[];
    const uint32_t sb = smem_u32(smem);
    const int tid = threadIdx.x, w = tid >> 5, lid = tid & 31;
    const int g = lid >> 2, t = lid & 3;

    const int bhq = blockIdx.x, qi = bhq & 255, bh = bhq >> 8;
    const size_t base = (size_t)bh * NQ * DD;
    const float* Qrow = q  + base + (size_t)qi * DD;
    const float* K1g  = k1 + base;
    const float* V1g  = v1 + base;
    const float* K2g  = k2 + base;
    const float* V2g  = v2 + base;

    // ---- prefetch panel 0 raw K1/V1 (16 KB each) via cp.async ----
    {
        const char* gK = (const char*)K1g;
        const char* gV = (const char*)V1g;
        for (int i = tid; i < 1024; i += 256) {
            cp16(sb + OFF_RAWK + (uint32_t)i * 16, gK + (size_t)i * 16);
            cp16(sb + OFF_RAWV + (uint32_t)i * 16, gV + (size_t)i * 16);
        }
        cp_commit();
    }

    const int dp = tid & 31;
    // ---- stage K2 hi/lo (overlaps cp.async flight) ----
    {
        const float2* K2g2 = (const float2*)K2g;
        for (int e2 = tid; e2 < NQ * 32; e2 += 256) {
            const int r = e2 >> 5;
            const float2 x = K2g2[e2];
            uint32_t h, l; split2(x.x, x.y, h, l);
            const uint32_t off = SWZ((uint32_t)r * 128 + (uint32_t)dp * 4);
            *(uint32_t*)(smem + OFF_K2H + off) = h;
            *(uint32_t*)(smem + OFF_K2L + off) = l;
        }
    }

    const float2 qme = ((const float2*)Qrow)[dp];
    const float qx = qme.x * 1.4426950408889634f;
    const float qy = qme.y * 1.4426950408889634f;

    const uint32_t lmA_r = (uint32_t)(lid & 15), lmA_c = (uint32_t)(lid >> 4) * 16;
    const uint32_t lmB_r = (uint32_t)((lid >> 4) * 8 + (lid & 7)), lmB_c = (uint32_t)((lid >> 3) & 1) * 16;

    float o[2][8][4];
    #pragma unroll
    for (int mt = 0; mt < 2; ++mt)
        #pragma unroll
        for (int nt = 0; nt < 8; ++nt)
            #pragma unroll
            for (int r = 0; r < 4; ++r) o[mt][nt][r] = 0.f;
    float lsum = 0.f;
    float mrun = -1e30f;                 // running per-warp max (log2 units)

    #pragma unroll 1
    for (int p = 0; p < NPANEL; ++p) {
        cp_wait0();
        __syncthreads();

        // ---- convert raw panel p: Qh (bf16 hi/lo) and V1 (fp16 single) ----
        {
            const float2* rk = (const float2*)(smem + OFF_RAWK + (uint32_t)(p & 1) * 16384);
            const float2* rv = (const float2*)(smem + OFF_RAWV + (uint32_t)(p & 1) * 16384);
            for (int e2 = tid; e2 < 64 * 32; e2 += 256) {
                const int r = e2 >> 5;
                const uint32_t off = SWZ((uint32_t)r * 128 + (uint32_t)dp * 4);
                {
                    const float2 x = rk[e2];
                    uint32_t h, l; split2(qx * x.x, qy * x.y, h, l);
                    *(uint32_t*)(smem + OFF_QHH + off) = h;
                    *(uint32_t*)(smem + OFF_QHL + off) = l;
                }
                {
                    const float2 x = rv[e2];
                    const __half2 hh = __floats2half2_rn(x.x, x.y);
                    *(uint32_t*)(smem + OFF_V1H + off) = *(const uint32_t*)&hh;
                }
            }
        }
        if (p < NPANEL - 1) {            // prefetch panel p+1 raw
            const char* gK = (const char*)(K1g + (size_t)(p + 1) * 64 * DD);
            const char* gV = (const char*)(V1g + (size_t)(p + 1) * 64 * DD);
            const uint32_t rb = (uint32_t)((p + 1) & 1) * 16384;
            for (int i = tid; i < 1024; i += 256) {
                cp16(sb + OFF_RAWK + rb + (uint32_t)i * 16, gK + (size_t)i * 16);
                cp16(sb + OFF_RAWV + rb + (uint32_t)i * 16, gV + (size_t)i * 16);
            }
            cp_commit();
        }
        __syncthreads();

        // ---- GEMM1: S[k32(w), j64] in log2 units (bf16 hi/lo, 3 products) ----
        float s[2][8][4];
        #pragma unroll
        for (int mt = 0; mt < 2; ++mt)
            #pragma unroll
            for (int nt = 0; nt < 8; ++nt)
                #pragma unroll
                for (int r = 0; r < 4; ++r) s[mt][nt][r] = 0.f;

        #pragma unroll
        for (int kc = 0; kc < 4; ++kc) {
            uint32_t aH[2][4], aL[2][4];
            #pragma unroll
            for (int mt = 0; mt < 2; ++mt) {
                const uint32_t rb = (uint32_t)(32 * w + 16 * mt + lmA_r) * 128
                                  + (uint32_t)kc * 32 + lmA_c;
                ldsm_x4(aH[mt], sb + OFF_K2H + SWZ(rb));
                ldsm_x4(aL[mt], sb + OFF_K2L + SWZ(rb));
            }
            #pragma unroll
            for (int cp = 0; cp < 4; ++cp) {
                uint32_t bH[4], bL[4];
                const uint32_t rb = (uint32_t)(16 * cp + lmB_r) * 128
                                  + (uint32_t)kc * 32 + lmB_c;
                ldsm_x4(bH, sb + OFF_QHH + SWZ(rb));
                ldsm_x4(bL, sb + OFF_QHL + SWZ(rb));
                #pragma unroll
                for (int h = 0; h < 2; ++h)
                    #pragma unroll
                    for (int mt = 0; mt < 2; ++mt)
                        mma_bf(s[mt][2*cp+h], aH[mt], bH[2*h], bH[2*h+1]);
                #pragma unroll
                for (int h = 0; h < 2; ++h)
                    #pragma unroll
                    for (int mt = 0; mt < 2; ++mt)
                        mma_bf(s[mt][2*cp+h], aH[mt], bL[2*h], bL[2*h+1]);
                #pragma unroll
                for (int h = 0; h < 2; ++h)
                    #pragma unroll
                    for (int mt = 0; mt < 2; ++mt)
                        mma_bf(s[mt][2*cp+h], aL[mt], bH[2*h], bH[2*h+1]);
            }
        }

        // ---- online max update: warp-wide max of this panel's logits ----
        {
            float pm = s[0][0][0];
            #pragma unroll
            for (int mt = 0; mt < 2; ++mt)
                #pragma unroll
                for (int nt = 0; nt < 8; ++nt)
                    #pragma unroll
                    for (int r = 0; r < 4; ++r) pm = fmaxf(pm, s[mt][nt][r]);
            #pragma unroll
            for (int m = 16; m; m >>= 1)
                pm = fmaxf(pm, __shfl_xor_sync(0xffffffffu, pm, m));
            const float mnew = fmaxf(mrun, pm);
            const float rsc = ex2f(mrun - mnew);     // 0 on first panel
            lsum *= rsc;
            #pragma unroll
            for (int mt = 0; mt < 2; ++mt)
                #pragma unroll
                for (int nt = 0; nt < 8; ++nt)
                    #pragma unroll
                    for (int r = 0; r < 4; ++r) o[mt][nt][r] *= rsc;
            mrun = mnew;
        }

        // ---- per j16-chunk: exp2(s - m) -> fp16 P (<=1), GEMM2 fp16 1-product ----
        #pragma unroll
        for (int c = 0; c < 4; ++c) {
            uint32_t paH[2][4];
            #pragma unroll
            for (int mt = 0; mt < 2; ++mt) {
                #pragma unroll
                for (int h = 0; h < 2; ++h) {
                    float* cc = s[mt][2 * c + h];
                    const float p0 = ex2f(cc[0] - mrun);
                    const float p1 = ex2f(cc[1] - mrun);
                    const float p2 = ex2f(cc[2] - mrun);
                    const float p3 = ex2f(cc[3] - mrun);
                    lsum += (p0 + p1) + (p2 + p3);
                    paH[mt][2*h]   = packh2_sat(p0, p1);   // rows g
                    paH[mt][2*h+1] = packh2_sat(p2, p3);   // rows g+8
                }
            }
            #pragma unroll
            for (int ntp = 0; ntp < 4; ++ntp) {
                uint32_t vH[4];
                const uint32_t rb = (uint32_t)(16 * c + lmA_r) * 128
                                  + (uint32_t)ntp * 32 + lmA_c;
                ldsm_x4_t(vH, sb + OFF_V1H + SWZ(rb));
                #pragma unroll
                for (int h = 0; h < 2; ++h)
                    #pragma unroll
                    for (int mt = 0; mt < 2; ++mt)
                        mma_hf(o[mt][2*ntp+h], paH[mt], vH[2*h], vH[2*h+1]);
            }
        }
    }

    // ---- epilogue: combine warps with per-warp max rescale ----
    float* sRed = (float*)(smem + OFF_SRED);
    float* sLp  = (float*)(smem + OFF_SLP);
    float* sM   = (float*)(smem + OFF_SM);
    {
        const int k0 = 32 * w + g;
        #pragma unroll
        for (int nt = 0; nt < 8; ++nt) {
            const int d0 = 8 * nt + 2 * t;
            const float2 vA = *(const float2*)(V2g + (size_t)(k0)      * DD + d0);
            const float2 vB = *(const float2*)(V2g + (size_t)(k0 + 8)  * DD + d0);
            const float2 vC = *(const float2*)(V2g + (size_t)(k0 + 16) * DD + d0);
            const float2 vD = *(const float2*)(V2g + (size_t)(k0 + 24) * DD + d0);
            float r0 = o[0][nt][0]*vA.x + o[0][nt][2]*vB.x + o[1][nt][0]*vC.x + o[1][nt][2]*vD.x;
            float r1 = o[0][nt][1]*vA.y + o[0][nt][3]*vB.y + o[1][nt][1]*vC.y + o[1][nt][3]*vD.y;
            #pragma unroll
            for (int m = 4; m <= 16; m <<= 1) {
                r0 += __shfl_xor_sync(0xffffffffu, r0, m);
                r1 += __shfl_xor_sync(0xffffffffu, r1, m);
            }
            if (g == 0) *(float2*)(sRed + w * 64 + d0) = make_float2(r0, r1);
        }
        #pragma unroll
        for (int m = 16; m; m >>= 1)
            lsum += __shfl_xor_sync(0xffffffffu, lsum, m);
        if (lid == 0) { sLp[w] = lsum; sM[w] = mrun; }
    }
    __syncthreads();

    if (tid < 64) {
        float M = sM[0];
        #pragma unroll
        for (int ww = 1; ww < 8; ++ww) M = fmaxf(M, sM[ww]);
        float ssum = 0.f, l = 0.f;
        #pragma unroll
        for (int ww = 0; ww < 8; ++ww) {
            const float sc = ex2f(sM[ww] - M);
            ssum += sc * sRed[ww * 64 + tid];
            l    += sc * sLp[ww];
        }
        out[base + (size_t)qi * DD + tid] = ssum / l;
    }
}

extern "C" void kernel_launch(void* const* d_in, const int* in_sizes, int n_in,
                              void* d_out, int out_size)
{
    const float* q  = (const float*)d_in[0];
    const float* k1 = (const float*)d_in[1];
    const float* v1 = (const float*)d_in[2];
    const float* k2 = (const float*)d_in[3];
    const float* v2 = (const float*)d_in[4];
    float* out = (float*)d_out;

    (void)cudaFuncSetAttribute(trisimp_mma5_kernel,
                               cudaFuncAttributeMaxDynamicSharedMemorySize, SMEM_BYTES);
    trisimp_mma5_kernel<<<2 * 8 * NQ, 256, SMEM_BYTES>>>(q, k1, v1, k2, v2, out);
}